// round 17
// baseline (speedup 1.0000x reference)
#include <cuda_runtime.h>
#include <cuda_bf16.h>

#define NN 10000
#define NE 640000
#define C 128
#define NH 8
#define HD 16
#define BD 32
#define NEG_SLOPE 0.01f
#define TILE_E 128

// ---------------- packed f32x2 helpers (FFMA2 — only reachable via PTX) ----
#define FMA_F32X2(d, a, b, c) \
    asm("fma.rn.f32x2 %0, %1, %2, %3;" : "=l"(d) : "l"(a), "l"(b), "l"(c))

__device__ __forceinline__ unsigned long long pack2(float lo, float hi) {
    unsigned long long r;
    asm("mov.b64 %0, {%1, %2};" : "=l"(r) : "f"(lo), "f"(hi));
    return r;
}
__device__ __forceinline__ void unpack2(unsigned long long v, float& lo, float& hi) {
    asm("mov.b64 {%0, %1}, %2;" : "=f"(lo), "=f"(hi) : "l"(v));
}

// ---------------- scratch (device globals; no allocation allowed) ----------
__device__ float g_Q[NN * C];
__device__ float g_K[NN * C];
__device__ float g_V[NN * C];
__device__ int   g_cnt[NN];
__device__ int   g_off[NN + 1];
__device__ int   g_cur[NN];
__device__ int2  g_slot[NE];          // {edge, src}
__device__ float g_ex[NE * NH];       // indexed by RAW edge id

// ---------------- node projection GEMM: Out[M,128] = A[M,128] @ W[128,128] -
__global__ __launch_bounds__(256) void k_gemm128(
        const float* __restrict__ A, const float* __restrict__ W,
        float* __restrict__ Out, int M) {
    __shared__ __align__(16) float2 sA2[64][32];   // duplicated (v,v) -> 16KB
    __shared__ __align__(16) float  sW[32][C];     // 16KB
    int tid = threadIdx.x;
    int tx = tid & 31;       // column group (4 cols each)
    int ty = tid >> 5;       // row group (8 rows each)
    int row0 = blockIdx.x * 64;

    unsigned long long acc[8][2];
#pragma unroll
    for (int i = 0; i < 8; i++) { acc[i][0] = 0ull; acc[i][1] = 0ull; }

    for (int kt = 0; kt < C; kt += 32) {
        for (int i = tid; i < 64 * 32; i += 256) {
            int r = i >> 5, k = i & 31;
            float a = (row0 + r < M) ? A[(row0 + r) * C + kt + k] : 0.0f;
            sA2[r][k] = make_float2(a, a);
        }
        for (int i = tid; i < 32 * C; i += 256) {
            int k = i >> 7, c = i & 127;
            sW[k][c] = W[(kt + k) * C + c];
        }
        __syncthreads();
#pragma unroll
        for (int kk = 0; kk < 32; kk++) {
            ulonglong2 b2 = *(const ulonglong2*)&sW[kk][tx * 4];
#pragma unroll
            for (int i = 0; i < 8; i++) {
                unsigned long long aa = *(const unsigned long long*)&sA2[ty * 8 + i][kk];
                FMA_F32X2(acc[i][0], aa, b2.x, acc[i][0]);
                FMA_F32X2(acc[i][1], aa, b2.y, acc[i][1]);
            }
        }
        __syncthreads();
    }
#pragma unroll
    for (int i = 0; i < 8; i++) {
        int r = row0 + ty * 8 + i;
        if (r < M) {
            float4 o;
            unpack2(acc[i][0], o.x, o.y);
            unpack2(acc[i][1], o.z, o.w);
            *(float4*)&Out[r * C + tx * 4] = o;
        }
    }
}

// ---------------- edge pass: tiled GEMM + logits + exp ---------------------
// Tile = 128 edges x 128 channels per 256-thread block.
// Thread = 16 edges (ty) x 4 channels (tx).
// Phase 1: quad cf broadcasts (LDS.128) x register-blocked W.
// Phase 2a: Q/K gathers for ALL 16 edges batched (independent LDG.128 pairs,
//           folded into acc in place) -> L2 latency paid once, not 16x.
// Phase 2b: register-only epilogue.
__global__ __launch_bounds__(256, 2) void k_edge(
        const float* __restrict__ edge_attrs,
        const int*   __restrict__ esrc,
        const int*   __restrict__ edst,
        const float* __restrict__ W_E,
        const float* __restrict__ att) {
    __shared__ __align__(16) float  sWE[BD][C];           // 16KB, loaded once
    __shared__ __align__(16) float4 sEA[TILE_E][BD / 4];  // 16KB, raw quads
    __shared__ int2 sIdx[TILE_E];                         // {src, dst}

    int tid = threadIdx.x;
    int tx  = tid & 31;      // channel group (4 channels: tx*4..tx*4+3)
    int ty  = tid >> 5;      // edge group (16 edges) == warp id

    for (int i = tid; i < BD * C; i += 256) sWE[i >> 7][i & 127] = W_E[i];
    float4 a = ((const float4*)att)[tx];   // this lane's 4 att coeffs

    const int NT = NE / TILE_E;   // 5000 tiles
    for (int tile = blockIdx.x; tile < NT; tile += gridDim.x) {
        long long e0 = (long long)tile * TILE_E;
        __syncthreads();
        // stage coefficients as raw float4 quads (coalesced) + indices
        for (int i = tid; i < TILE_E * (BD / 4); i += 256) {
            sEA[i >> 3][i & 7] = ((const float4*)edge_attrs)[e0 * (BD / 4) + i];
        }
        if (tid < TILE_E) sIdx[tid] = make_int2(esrc[e0 + tid], edst[e0 + tid]);
        __syncthreads();

        // ---- phase 1: E-projection GEMM (16 edges x 4 channels / thread) --
        unsigned long long acc[16][2];
#pragma unroll
        for (int e = 0; e < 16; e++) { acc[e][0] = 0ull; acc[e][1] = 0ull; }
#pragma unroll 1
        for (int kq = 0; kq < BD / 4; kq++) {
            // W for 4 consecutive k's, this thread's 4 channels
            ulonglong2 w0 = *(const ulonglong2*)&sWE[4 * kq + 0][tx * 4];
            ulonglong2 w1 = *(const ulonglong2*)&sWE[4 * kq + 1][tx * 4];
            ulonglong2 w2 = *(const ulonglong2*)&sWE[4 * kq + 2][tx * 4];
            ulonglong2 w3 = *(const ulonglong2*)&sWE[4 * kq + 3][tx * 4];
#pragma unroll
            for (int e = 0; e < 16; e++) {
                float4 cf = sEA[ty * 16 + e][kq];     // broadcast LDS.128
                unsigned long long c0 = pack2(cf.x, cf.x);
                unsigned long long c1 = pack2(cf.y, cf.y);
                unsigned long long c2 = pack2(cf.z, cf.z);
                unsigned long long c3 = pack2(cf.w, cf.w);
                FMA_F32X2(acc[e][0], c0, w0.x, acc[e][0]);
                FMA_F32X2(acc[e][1], c0, w0.y, acc[e][1]);
                FMA_F32X2(acc[e][0], c1, w1.x, acc[e][0]);
                FMA_F32X2(acc[e][1], c1, w1.y, acc[e][1]);
                FMA_F32X2(acc[e][0], c2, w2.x, acc[e][0]);
                FMA_F32X2(acc[e][1], c2, w2.y, acc[e][1]);
                FMA_F32X2(acc[e][0], c3, w3.x, acc[e][0]);
                FMA_F32X2(acc[e][1], c3, w3.y, acc[e][1]);
            }
        }

        // ---- phase 2a: fold Q[dst]+K[src] into acc (batched, high MLP) ----
#pragma unroll
        for (int e = 0; e < 16; e++) {
            int2 id = sIdx[ty * 16 + e];
            float4 q  = ((const float4*)g_Q)[id.y * 32 + tx];
            float4 k4 = ((const float4*)g_K)[id.x * 32 + tx];
            float ax, ay, az, aw;
            unpack2(acc[e][0], ax, ay);
            unpack2(acc[e][1], az, aw);
            acc[e][0] = pack2(ax + q.x + k4.x, ay + q.y + k4.y);
            acc[e][1] = pack2(az + q.z + k4.z, aw + q.w + k4.w);
        }

        // ---- phase 2b: leaky-relu + logits + exp (register-only) ----------
#pragma unroll
        for (int e = 0; e < 16; e++) {
            float sx, sy, sz, sw;
            unpack2(acc[e][0], sx, sy);
            unpack2(acc[e][1], sz, sw);
            sx = fmaxf(sx, 0.f) + NEG_SLOPE * fminf(sx, 0.f);
            sy = fmaxf(sy, 0.f) + NEG_SLOPE * fminf(sy, 0.f);
            sz = fmaxf(sz, 0.f) + NEG_SLOPE * fminf(sz, 0.f);
            sw = fmaxf(sw, 0.f) + NEG_SLOPE * fminf(sw, 0.f);
            float p = sx * a.x + sy * a.y + sz * a.z + sw * a.w;
            p += __shfl_xor_sync(0xffffffffu, p, 1);
            p += __shfl_xor_sync(0xffffffffu, p, 2);
            if ((tx & 3) == 0) {
                g_ex[(e0 + ty * 16 + e) * NH + (tx >> 2)] = __expf(p);
            }
        }
    }
}

// ---------------- CSR build ------------------------------------------------
__global__ void k_zero_cnt() {
    int i = blockIdx.x * blockDim.x + threadIdx.x;
    if (i < NN) g_cnt[i] = 0;
}

__global__ void k_hist(const int* __restrict__ dst) {
    int i = blockIdx.x * blockDim.x + threadIdx.x;
    if (i < NE) atomicAdd(&g_cnt[dst[i]], 1);
}

__global__ void k_scan() {
    __shared__ int warp_tot[32];
    __shared__ int carry_s;
    int tid = threadIdx.x, lane = tid & 31, wid = tid >> 5;
    if (tid == 0) carry_s = 0;
    __syncthreads();
    for (int base = 0; base < NN; base += 1024) {
        int idx = base + tid;
        int v = (idx < NN) ? g_cnt[idx] : 0;
        int x = v;
#pragma unroll
        for (int of = 1; of < 32; of <<= 1) {
            int t = __shfl_up_sync(0xffffffffu, x, of);
            if (lane >= of) x += t;
        }
        if (lane == 31) warp_tot[wid] = x;
        __syncthreads();
        if (wid == 0) {
            int w = warp_tot[lane];
#pragma unroll
            for (int of = 1; of < 32; of <<= 1) {
                int t = __shfl_up_sync(0xffffffffu, w, of);
                if (lane >= of) w += t;
            }
            warp_tot[lane] = w;
        }
        __syncthreads();
        int incl = x + ((wid > 0) ? warp_tot[wid - 1] : 0);
        int excl = carry_s + incl - v;
        if (idx < NN) { g_off[idx] = excl; g_cur[idx] = excl; }
        int tot = warp_tot[31];
        __syncthreads();
        if (tid == 0) carry_s += tot;
        __syncthreads();
    }
    if (threadIdx.x == 0) g_off[NN] = NE;
}

__global__ void k_fill(const int* __restrict__ src, const int* __restrict__ dst) {
    int i = blockIdx.x * blockDim.x + threadIdx.x;
    if (i < NE) {
        int d = dst[i];
        int s = src[i];
        int pos = atomicAdd(&g_cur[d], 1);
        g_slot[pos] = make_int2(i, s);
    }
}

// ---------------- per-node softmax-normalize + weighted aggregate ----------
#define NCHUNK 64
__global__ __launch_bounds__(128) void k_node(float* __restrict__ out) {
    int v = blockIdx.x;
    int tid = threadIdx.x;
    int s0 = g_off[v];
    int s1 = g_off[v + 1];

    __shared__ int2  sSlot[NCHUNK];
    __shared__ float sEx[NCHUNK * NH];
    __shared__ float sden[NH];
    __shared__ float rden[NH];
    if (tid < NH) sden[tid] = 0.0f;

    int h = tid >> 4;        // head of this output channel
    int hh = tid & 7;        // head this thread accumulates denominator for
    float d = 0.0f;
    float acc = 0.0f;

    for (int c = s0; c < s1; c += NCHUNK) {
        int n = min(NCHUNK, s1 - c);
        __syncthreads();
        if (tid < n) sSlot[tid] = g_slot[c + tid];
        __syncthreads();
        for (int i = tid; i < n * NH; i += 128) {
            int jj = i >> 3;
            sEx[i] = g_ex[(long long)sSlot[jj].x * NH + (i & 7)];
        }
        __syncthreads();

        for (int i = tid; i < n * NH; i += 128) d += sEx[i];

        int j = 0;
        for (; j + 3 < n; j += 4) {
            float w0 = sEx[(j + 0) * NH + h];
            float w1 = sEx[(j + 1) * NH + h];
            float w2 = sEx[(j + 2) * NH + h];
            float w3 = sEx[(j + 3) * NH + h];
            float v0 = g_V[sSlot[j + 0].y * C + tid];
            float v1 = g_V[sSlot[j + 1].y * C + tid];
            float v2 = g_V[sSlot[j + 2].y * C + tid];
            float v3 = g_V[sSlot[j + 3].y * C + tid];
            acc += w0 * v0 + w1 * v1 + w2 * v2 + w3 * v3;
        }
        for (; j < n; j++) {
            acc += sEx[j * NH + h] * g_V[sSlot[j].y * C + tid];
        }
    }

    atomicAdd(&sden[hh], d);
    __syncthreads();
    if (tid < NH) rden[tid] = (sden[tid] > 0.0f) ? (1.0f / sden[tid]) : 0.0f;
    __syncthreads();

    out[v * C + tid] = acc * rden[h];
}

// ---------------- launch ---------------------------------------------------
extern "C" void kernel_launch(void* const* d_in, const int* in_sizes, int n_in,
                              void* d_out, int out_size) {
    const float* senders    = (const float*)d_in[0];
    const float* receivers  = (const float*)d_in[1];
    const int*   edge_idx   = (const int*)d_in[2];
    const float* edge_attrs = (const float*)d_in[3];
    const float* W_Q        = (const float*)d_in[4];
    const float* W_K        = (const float*)d_in[5];
    const float* W_V        = (const float*)d_in[6];
    const float* W_E        = (const float*)d_in[7];
    const float* att        = (const float*)d_in[8];
    float* out = (float*)d_out;

    const int* src = edge_idx;
    const int* dst = edge_idx + NE;

    float* dQ; cudaGetSymbolAddress((void**)&dQ, g_Q);
    float* dK; cudaGetSymbolAddress((void**)&dK, g_K);
    float* dV; cudaGetSymbolAddress((void**)&dV, g_V);

    // node projections (1-3)
    int gblocks = (NN + 63) / 64;
    k_gemm128<<<gblocks, 256>>>(receivers, W_Q, dQ, NN);
    k_gemm128<<<gblocks, 256>>>(senders,   W_K, dK, NN);
    k_gemm128<<<gblocks, 256>>>(senders,   W_V, dV, NN);

    // edge pass (4th launch — profiled slot): batched-gather epilogue
    k_edge<<<1480, 256>>>(edge_attrs, src, dst, W_E, att);

    // CSR build (5-8)
    k_zero_cnt<<<(NN + 255) / 256, 256>>>();
    k_hist<<<(NE + 255) / 256, 256>>>(dst);
    k_scan<<<1, 1024>>>();
    k_fill<<<(NE + 255) / 256, 256>>>(src, dst);

    // node aggregation (9)
    k_node<<<NN, 128>>>(out);
}